// round 5
// baseline (speedup 1.0000x reference)
#include <cuda_runtime.h>
#include <cuda_fp16.h>

#define N_NODES   50000
#define N_EDGES   800000
#define F_IN      16
#define F_EDGE    8
#define H         8
#define NUM_GRAPHS 512

// Q (o-major, fp16): Q[n][j*8+f], row = 64 halves = 128 B, line-aligned.
__device__ __align__(128) __half g_Qh[N_NODES * 64];       // 6.4 MB
__device__ __align__(16)  float  g_bias[N_NODES * H];      // 1.6 MB  (x@Be per node)
__device__ __align__(16)  float  g_agg1[N_NODES * H];      // 1.6 MB
__device__ __align__(16)  float  g_agg2[N_NODES * H];      // 1.6 MB

// ---------------------------------------------------------------------------
// Layer-1 node precompute (8 lanes per node, lane j = output channel j):
//   Qh[n][j*8+f] = sum_i x[n,i]*We1[f, i*8+j]    (fp16, o-major)
//   bias[n][j]   = sum_i x[n,i]*be1[i*8+j]
//   agg1[n][j]   = x[n]@root1[:,j] + b1[j]
// ---------------------------------------------------------------------------
__global__ void node1_kernel(const float* __restrict__ x,
                             const float* __restrict__ We1,
                             const float* __restrict__ be1,
                             const float* __restrict__ root1,
                             const float* __restrict__ b1) {
    __shared__ float sW[F_EDGE * F_IN * H];  // 1024
    __shared__ float sR[F_IN * H];           // 128
    __shared__ float sB[F_IN * H];           // 128
    __shared__ float sb[H];
    for (int i = threadIdx.x; i < F_EDGE * F_IN * H; i += blockDim.x) sW[i] = We1[i];
    for (int i = threadIdx.x; i < F_IN * H; i += blockDim.x) { sR[i] = root1[i]; sB[i] = be1[i]; }
    if (threadIdx.x < H) sb[threadIdx.x] = b1[threadIdx.x];
    __syncthreads();

    int gid = blockIdx.x * blockDim.x + threadIdx.x;
    int n = gid >> 3, j = gid & 7;
    if (n >= N_NODES) return;

    float xv[F_IN];
    const float4* xp = (const float4*)(x + n * F_IN);
    #pragma unroll
    for (int v = 0; v < 4; v++) {
        float4 t = xp[v];
        xv[v * 4 + 0] = t.x; xv[v * 4 + 1] = t.y; xv[v * 4 + 2] = t.z; xv[v * 4 + 3] = t.w;
    }

    float q[8];
    #pragma unroll
    for (int f = 0; f < 8; f++) {
        float s = 0.f;
        #pragma unroll
        for (int i = 0; i < F_IN; i++) s = fmaf(xv[i], sW[f * 128 + i * 8 + j], s);
        q[f] = s;
    }
    union { uint4 u; __half2 h[4]; } pk;
    pk.h[0] = __floats2half2_rn(q[0], q[1]);
    pk.h[1] = __floats2half2_rn(q[2], q[3]);
    pk.h[2] = __floats2half2_rn(q[4], q[5]);
    pk.h[3] = __floats2half2_rn(q[6], q[7]);
    *(uint4*)(g_Qh + n * 64 + j * 8) = pk.u;

    float qb = 0.f, r = sb[j];
    #pragma unroll
    for (int i = 0; i < F_IN; i++) {
        qb = fmaf(xv[i], sB[i * 8 + j], qb);
        r  = fmaf(xv[i], sR[i * 8 + j], r);
    }
    g_bias[n * 8 + j] = qb;
    g_agg1[n * 8 + j] = r;
}

// ---------------------------------------------------------------------------
// Layer-2 node precompute: h = relu(agg1); same structure
// ---------------------------------------------------------------------------
__global__ void node2_kernel(const float* __restrict__ We2,
                             const float* __restrict__ be2,
                             const float* __restrict__ root2,
                             const float* __restrict__ b2) {
    __shared__ float sW[F_EDGE * H * H];  // 512
    __shared__ float sR[H * H];           // 64
    __shared__ float sB[H * H];           // 64
    __shared__ float sb[H];
    for (int i = threadIdx.x; i < F_EDGE * H * H; i += blockDim.x) sW[i] = We2[i];
    for (int i = threadIdx.x; i < H * H; i += blockDim.x) { sR[i] = root2[i]; sB[i] = be2[i]; }
    if (threadIdx.x < H) sb[threadIdx.x] = b2[threadIdx.x];
    __syncthreads();

    int gid = blockIdx.x * blockDim.x + threadIdx.x;
    int n = gid >> 3, j = gid & 7;
    if (n >= N_NODES) return;

    float h[H];
    const float4* hp = (const float4*)(g_agg1 + n * 8);
    float4 a0 = hp[0], a1 = hp[1];
    h[0] = fmaxf(a0.x, 0.f); h[1] = fmaxf(a0.y, 0.f);
    h[2] = fmaxf(a0.z, 0.f); h[3] = fmaxf(a0.w, 0.f);
    h[4] = fmaxf(a1.x, 0.f); h[5] = fmaxf(a1.y, 0.f);
    h[6] = fmaxf(a1.z, 0.f); h[7] = fmaxf(a1.w, 0.f);

    float q[8];
    #pragma unroll
    for (int f = 0; f < 8; f++) {
        float s = 0.f;
        #pragma unroll
        for (int i = 0; i < H; i++) s = fmaf(h[i], sW[f * 64 + i * 8 + j], s);
        q[f] = s;
    }
    union { uint4 u; __half2 hh[4]; } pk;
    pk.hh[0] = __floats2half2_rn(q[0], q[1]);
    pk.hh[1] = __floats2half2_rn(q[2], q[3]);
    pk.hh[2] = __floats2half2_rn(q[4], q[5]);
    pk.hh[3] = __floats2half2_rn(q[6], q[7]);
    *(uint4*)(g_Qh + n * 64 + j * 8) = pk.u;

    float qb = 0.f, r = sb[j];
    #pragma unroll
    for (int i = 0; i < H; i++) {
        qb = fmaf(h[i], sB[i * 8 + j], qb);
        r  = fmaf(h[i], sR[i * 8 + j], r);
    }
    g_bias[n * 8 + j] = qb;
    g_agg2[n * 8 + j] = r;
}

// ---------------------------------------------------------------------------
// Edge pass: 8 lanes per edge, 2 edges per thread, fp16 Q (layout unchanged
// from R4 — proven). New: collect the 8 per-channel sums into lanes j%4==0
// with 3 shuffles and issue ONE red.global.add.v4.f32 per 4 channels,
// cutting atomic lanes 4x (6.4M -> 1.6M per pass).
// ---------------------------------------------------------------------------
#define EPT 2
#define HALF_E (N_EDGES / EPT)

__device__ __forceinline__ void red_add_v4(float* p, float r0, float r1, float r2, float r3) {
    asm volatile(
        "{ .reg .u64 pg; cvta.to.global.u64 pg, %0;\n\t"
        "  red.global.add.v4.f32 [pg], {%1, %2, %3, %4}; }"
        :: "l"(p), "f"(r0), "f"(r1), "f"(r2), "f"(r3) : "memory");
}

__global__ void __launch_bounds__(256) edge_kernel(const int* __restrict__ ei,
                                                   const float* __restrict__ ea,
                                                   int layer) {
    int gid = blockIdx.x * blockDim.x + threadIdx.x;
    int e0 = gid >> 3, j = gid & 7;
    float* agg = layer ? g_agg2 : g_agg1;

    #pragma unroll
    for (int k = 0; k < EPT; k++) {
        int e = e0 + k * HALF_E;
        int s = __ldg(&ei[e]);
        int d = __ldg(&ei[N_EDGES + e]);

        const float4* eap = (const float4*)(ea + e * 8);
        float4 a0 = __ldg(eap);
        float4 a1 = __ldg(eap + 1);

        uint4 qraw = __ldg((const uint4*)(g_Qh + s * 64 + j * 8));
        union { uint4 u; __half2 h[4]; } qk; qk.u = qraw;
        float2 f0 = __half22float2(qk.h[0]);
        float2 f1 = __half22float2(qk.h[1]);
        float2 f2 = __half22float2(qk.h[2]);
        float2 f3 = __half22float2(qk.h[3]);

        float r = __ldg(&g_bias[s * 8 + j]);
        r = fmaf(a0.x, f0.x, r);
        r = fmaf(a0.y, f0.y, r);
        r = fmaf(a0.z, f1.x, r);
        r = fmaf(a0.w, f1.y, r);
        r = fmaf(a1.x, f2.x, r);
        r = fmaf(a1.y, f2.y, r);
        r = fmaf(a1.z, f3.x, r);
        r = fmaf(a1.w, f3.y, r);

        // Collect channels: after round 1 every lane holds the ordered pair
        // (r_{2m}, r_{2m+1}) of its pair-group; round 2 pulls the partner
        // pair so lanes with (j&3)==0 hold channels j..j+3 in order.
        float p  = __shfl_xor_sync(0xffffffffu, r, 1, 32);
        float lo = (j & 1) ? p : r;
        float hi = (j & 1) ? r : p;
        float lo2 = __shfl_xor_sync(0xffffffffu, lo, 2, 32);
        float hi2 = __shfl_xor_sync(0xffffffffu, hi, 2, 32);
        if ((j & 3) == 0) {
            red_add_v4(agg + d * 8 + j, lo, hi, lo2, hi2);  // 16B-aligned
        }
    }
}

// ---------------------------------------------------------------------------
// Output init + fused relu / pool / readout with warp-aggregated atomics.
// ---------------------------------------------------------------------------
__global__ void out_init_kernel(const float* __restrict__ blast, float* __restrict__ out) {
    int g = blockIdx.x * blockDim.x + threadIdx.x;
    if (g < NUM_GRAPHS) out[g] = blast[0];
}

__global__ void final_kernel(const int* __restrict__ batch,
                             const float* __restrict__ Wlast,
                             float* __restrict__ out) {
    int n = blockIdx.x * blockDim.x + threadIdx.x;
    bool valid = (n < N_NODES);
    int nc = valid ? n : (N_NODES - 1);

    const float4* ap = (const float4*)(g_agg2 + nc * 8);
    float4 a0 = ap[0], a1 = ap[1];
    float v = 0.f;
    v = fmaf(fmaxf(a0.x, 0.f), __ldg(&Wlast[0]), v);
    v = fmaf(fmaxf(a0.y, 0.f), __ldg(&Wlast[1]), v);
    v = fmaf(fmaxf(a0.z, 0.f), __ldg(&Wlast[2]), v);
    v = fmaf(fmaxf(a0.w, 0.f), __ldg(&Wlast[3]), v);
    v = fmaf(fmaxf(a1.x, 0.f), __ldg(&Wlast[4]), v);
    v = fmaf(fmaxf(a1.y, 0.f), __ldg(&Wlast[5]), v);
    v = fmaf(fmaxf(a1.z, 0.f), __ldg(&Wlast[6]), v);
    v = fmaf(fmaxf(a1.w, 0.f), __ldg(&Wlast[7]), v);
    if (!valid) v = 0.f;

    int b = __ldg(&batch[nc]);
    int b0 = __shfl_sync(0xffffffffu, b, 0);
    if (__all_sync(0xffffffffu, b == b0)) {
        #pragma unroll
        for (int off = 16; off >= 1; off >>= 1)
            v += __shfl_xor_sync(0xffffffffu, v, off, 32);
        if ((threadIdx.x & 31) == 0) atomicAdd(&out[b0], v);
    } else {
        if (valid) atomicAdd(&out[b], v);
    }
}

// ---------------------------------------------------------------------------
extern "C" void kernel_launch(void* const* d_in, const int* in_sizes, int n_in,
                              void* d_out, int out_size) {
    const float* x     = (const float*)d_in[0];
    const int*   ei    = (const int*)  d_in[1];
    const float* ea    = (const float*)d_in[2];
    const int*   batch = (const int*)  d_in[3];
    const float* We1   = (const float*)d_in[4];
    const float* be1   = (const float*)d_in[5];
    const float* root1 = (const float*)d_in[6];
    const float* b1    = (const float*)d_in[7];
    const float* We2   = (const float*)d_in[8];
    const float* be2   = (const float*)d_in[9];
    const float* root2 = (const float*)d_in[10];
    const float* b2    = (const float*)d_in[11];
    const float* Wlast = (const float*)d_in[12];
    const float* blast = (const float*)d_in[13];
    float* out = (float*)d_out;

    const int TPB = 256;
    int node_blocks = (N_NODES * 8 + TPB - 1) / TPB;
    int edge_blocks = (HALF_E * 8) / TPB;           // 12500, exact
    int fin_blocks  = (N_NODES + TPB - 1) / TPB;

    node1_kernel<<<node_blocks, TPB>>>(x, We1, be1, root1, b1);
    edge_kernel<<<edge_blocks, TPB>>>(ei, ea, 0);
    node2_kernel<<<node_blocks, TPB>>>(We2, be2, root2, b2);
    edge_kernel<<<edge_blocks, TPB>>>(ei, ea, 1);
    out_init_kernel<<<(NUM_GRAPHS + TPB - 1) / TPB, TPB>>>(blast, out);
    final_kernel<<<fin_blocks, TPB>>>(batch, Wlast, out);
}

// round 6
// speedup vs baseline: 1.0730x; 1.0730x over previous
#include <cuda_runtime.h>
#include <cuda_fp16.h>

#define N_NODES   50000
#define N_EDGES   800000
#define F_IN      16
#define F_EDGE    8
#define H         8
#define NUM_GRAPHS 512

// Q (o-major, fp16): Q[n][j*8+f], row = 64 halves = 128 B, line-aligned.
__device__ __align__(128) __half g_Qh[N_NODES * 64];       // 6.4 MB
__device__ __align__(16)  float  g_bias[N_NODES * H];      // 1.6 MB  (x@Be per node)
__device__ __align__(16)  float  g_agg1[N_NODES * H];      // 1.6 MB
__device__ __align__(16)  float  g_agg2[N_NODES * H];      // 1.6 MB

// ---------------------------------------------------------------------------
// Layer-1 node precompute (8 lanes per node, lane j = output channel j):
//   Qh[n][j*8+f] = sum_i x[n,i]*We1[f, i*8+j]    (fp16, o-major)
//   bias[n][j]   = sum_i x[n,i]*be1[i*8+j]
//   agg1[n][j]   = x[n]@root1[:,j] + b1[j]
// ---------------------------------------------------------------------------
__global__ void node1_kernel(const float* __restrict__ x,
                             const float* __restrict__ We1,
                             const float* __restrict__ be1,
                             const float* __restrict__ root1,
                             const float* __restrict__ b1) {
    __shared__ float sW[F_EDGE * F_IN * H];  // 1024
    __shared__ float sR[F_IN * H];           // 128
    __shared__ float sB[F_IN * H];           // 128
    __shared__ float sb[H];
    for (int i = threadIdx.x; i < F_EDGE * F_IN * H; i += blockDim.x) sW[i] = We1[i];
    for (int i = threadIdx.x; i < F_IN * H; i += blockDim.x) { sR[i] = root1[i]; sB[i] = be1[i]; }
    if (threadIdx.x < H) sb[threadIdx.x] = b1[threadIdx.x];
    __syncthreads();

    int gid = blockIdx.x * blockDim.x + threadIdx.x;
    int n = gid >> 3, j = gid & 7;
    if (n >= N_NODES) return;

    float xv[F_IN];
    const float4* xp = (const float4*)(x + n * F_IN);
    #pragma unroll
    for (int v = 0; v < 4; v++) {
        float4 t = xp[v];
        xv[v * 4 + 0] = t.x; xv[v * 4 + 1] = t.y; xv[v * 4 + 2] = t.z; xv[v * 4 + 3] = t.w;
    }

    float q[8];
    #pragma unroll
    for (int f = 0; f < 8; f++) {
        float s = 0.f;
        #pragma unroll
        for (int i = 0; i < F_IN; i++) s = fmaf(xv[i], sW[f * 128 + i * 8 + j], s);
        q[f] = s;
    }
    union { uint4 u; __half2 h[4]; } pk;
    pk.h[0] = __floats2half2_rn(q[0], q[1]);
    pk.h[1] = __floats2half2_rn(q[2], q[3]);
    pk.h[2] = __floats2half2_rn(q[4], q[5]);
    pk.h[3] = __floats2half2_rn(q[6], q[7]);
    *(uint4*)(g_Qh + n * 64 + j * 8) = pk.u;

    float qb = 0.f, r = sb[j];
    #pragma unroll
    for (int i = 0; i < F_IN; i++) {
        qb = fmaf(xv[i], sB[i * 8 + j], qb);
        r  = fmaf(xv[i], sR[i * 8 + j], r);
    }
    g_bias[n * 8 + j] = qb;
    g_agg1[n * 8 + j] = r;
}

// ---------------------------------------------------------------------------
// Layer-2 node precompute: h = relu(agg1); same structure
// ---------------------------------------------------------------------------
__global__ void node2_kernel(const float* __restrict__ We2,
                             const float* __restrict__ be2,
                             const float* __restrict__ root2,
                             const float* __restrict__ b2) {
    __shared__ float sW[F_EDGE * H * H];  // 512
    __shared__ float sR[H * H];           // 64
    __shared__ float sB[H * H];           // 64
    __shared__ float sb[H];
    for (int i = threadIdx.x; i < F_EDGE * H * H; i += blockDim.x) sW[i] = We2[i];
    for (int i = threadIdx.x; i < H * H; i += blockDim.x) { sR[i] = root2[i]; sB[i] = be2[i]; }
    if (threadIdx.x < H) sb[threadIdx.x] = b2[threadIdx.x];
    __syncthreads();

    int gid = blockIdx.x * blockDim.x + threadIdx.x;
    int n = gid >> 3, j = gid & 7;
    if (n >= N_NODES) return;

    float h[H];
    const float4* hp = (const float4*)(g_agg1 + n * 8);
    float4 a0 = hp[0], a1 = hp[1];
    h[0] = fmaxf(a0.x, 0.f); h[1] = fmaxf(a0.y, 0.f);
    h[2] = fmaxf(a0.z, 0.f); h[3] = fmaxf(a0.w, 0.f);
    h[4] = fmaxf(a1.x, 0.f); h[5] = fmaxf(a1.y, 0.f);
    h[6] = fmaxf(a1.z, 0.f); h[7] = fmaxf(a1.w, 0.f);

    float q[8];
    #pragma unroll
    for (int f = 0; f < 8; f++) {
        float s = 0.f;
        #pragma unroll
        for (int i = 0; i < H; i++) s = fmaf(h[i], sW[f * 64 + i * 8 + j], s);
        q[f] = s;
    }
    union { uint4 u; __half2 hh[4]; } pk;
    pk.hh[0] = __floats2half2_rn(q[0], q[1]);
    pk.hh[1] = __floats2half2_rn(q[2], q[3]);
    pk.hh[2] = __floats2half2_rn(q[4], q[5]);
    pk.hh[3] = __floats2half2_rn(q[6], q[7]);
    *(uint4*)(g_Qh + n * 64 + j * 8) = pk.u;

    float qb = 0.f, r = sb[j];
    #pragma unroll
    for (int i = 0; i < H; i++) {
        qb = fmaf(h[i], sB[i * 8 + j], qb);
        r  = fmaf(h[i], sR[i * 8 + j], r);
    }
    g_bias[n * 8 + j] = qb;
    g_agg2[n * 8 + j] = r;
}

// ---------------------------------------------------------------------------
// Edge pass: 8 lanes per edge, EPT=4 edges per thread, fp16 Q.
// Two-phase: stage ALL loads for 4 edges (independent -> deep MLP), then
// compute + scalar atomicAdd (proven fastest reduction path).
// ---------------------------------------------------------------------------
#define EPT 4
#define QUARTER_E (N_EDGES / EPT)

__global__ void __launch_bounds__(256) edge_kernel(const int* __restrict__ ei,
                                                   const float* __restrict__ ea,
                                                   int layer) {
    int gid = blockIdx.x * blockDim.x + threadIdx.x;
    int e0 = gid >> 3, j = gid & 7;
    float* agg = layer ? g_agg2 : g_agg1;

    int   s[EPT], d[EPT];
    float4 a0[EPT], a1[EPT];
    uint4  qr[EPT];
    float  qb[EPT];

    // Phase 1: stage everything (indices first, then dependent gathers; all
    // 4 edges' chains independent -> up to 16 outstanding loads)
    #pragma unroll
    for (int k = 0; k < EPT; k++) {
        int e = e0 + k * QUARTER_E;
        s[k] = __ldg(&ei[e]);
        d[k] = __ldg(&ei[N_EDGES + e]);
    }
    #pragma unroll
    for (int k = 0; k < EPT; k++) {
        int e = e0 + k * QUARTER_E;
        const float4* eap = (const float4*)(ea + e * 8);
        a0[k] = __ldg(eap);
        a1[k] = __ldg(eap + 1);
        qr[k] = __ldg((const uint4*)(g_Qh + s[k] * 64 + j * 8));
        qb[k] = __ldg(&g_bias[s[k] * 8 + j]);
    }

    // Phase 2: compute + reduce
    #pragma unroll
    for (int k = 0; k < EPT; k++) {
        union { uint4 u; __half2 h[4]; } qk; qk.u = qr[k];
        float2 f0 = __half22float2(qk.h[0]);
        float2 f1 = __half22float2(qk.h[1]);
        float2 f2 = __half22float2(qk.h[2]);
        float2 f3 = __half22float2(qk.h[3]);

        float r = qb[k];
        r = fmaf(a0[k].x, f0.x, r);
        r = fmaf(a0[k].y, f0.y, r);
        r = fmaf(a0[k].z, f1.x, r);
        r = fmaf(a0[k].w, f1.y, r);
        r = fmaf(a1[k].x, f2.x, r);
        r = fmaf(a1[k].y, f2.y, r);
        r = fmaf(a1[k].z, f3.x, r);
        r = fmaf(a1[k].w, f3.y, r);

        atomicAdd(&agg[d[k] * 8 + j], r);
    }
}

// ---------------------------------------------------------------------------
// Output init + fused relu / pool / readout with warp-aggregated atomics.
// ---------------------------------------------------------------------------
__global__ void out_init_kernel(const float* __restrict__ blast, float* __restrict__ out) {
    int g = blockIdx.x * blockDim.x + threadIdx.x;
    if (g < NUM_GRAPHS) out[g] = blast[0];
}

__global__ void final_kernel(const int* __restrict__ batch,
                             const float* __restrict__ Wlast,
                             float* __restrict__ out) {
    int n = blockIdx.x * blockDim.x + threadIdx.x;
    bool valid = (n < N_NODES);
    int nc = valid ? n : (N_NODES - 1);

    const float4* ap = (const float4*)(g_agg2 + nc * 8);
    float4 a0 = ap[0], a1 = ap[1];
    float v = 0.f;
    v = fmaf(fmaxf(a0.x, 0.f), __ldg(&Wlast[0]), v);
    v = fmaf(fmaxf(a0.y, 0.f), __ldg(&Wlast[1]), v);
    v = fmaf(fmaxf(a0.z, 0.f), __ldg(&Wlast[2]), v);
    v = fmaf(fmaxf(a0.w, 0.f), __ldg(&Wlast[3]), v);
    v = fmaf(fmaxf(a1.x, 0.f), __ldg(&Wlast[4]), v);
    v = fmaf(fmaxf(a1.y, 0.f), __ldg(&Wlast[5]), v);
    v = fmaf(fmaxf(a1.z, 0.f), __ldg(&Wlast[6]), v);
    v = fmaf(fmaxf(a1.w, 0.f), __ldg(&Wlast[7]), v);
    if (!valid) v = 0.f;

    int b = __ldg(&batch[nc]);
    int b0 = __shfl_sync(0xffffffffu, b, 0);
    if (__all_sync(0xffffffffu, b == b0)) {
        #pragma unroll
        for (int off = 16; off >= 1; off >>= 1)
            v += __shfl_xor_sync(0xffffffffu, v, off, 32);
        if ((threadIdx.x & 31) == 0) atomicAdd(&out[b0], v);
    } else {
        if (valid) atomicAdd(&out[b], v);
    }
}

// ---------------------------------------------------------------------------
extern "C" void kernel_launch(void* const* d_in, const int* in_sizes, int n_in,
                              void* d_out, int out_size) {
    const float* x     = (const float*)d_in[0];
    const int*   ei    = (const int*)  d_in[1];
    const float* ea    = (const float*)d_in[2];
    const int*   batch = (const int*)  d_in[3];
    const float* We1   = (const float*)d_in[4];
    const float* be1   = (const float*)d_in[5];
    const float* root1 = (const float*)d_in[6];
    const float* b1    = (const float*)d_in[7];
    const float* We2   = (const float*)d_in[8];
    const float* be2   = (const float*)d_in[9];
    const float* root2 = (const float*)d_in[10];
    const float* b2    = (const float*)d_in[11];
    const float* Wlast = (const float*)d_in[12];
    const float* blast = (const float*)d_in[13];
    float* out = (float*)d_out;

    const int TPB = 256;
    int node_blocks = (N_NODES * 8 + TPB - 1) / TPB;
    int edge_blocks = (QUARTER_E * 8) / TPB;        // 6250, exact
    int fin_blocks  = (N_NODES + TPB - 1) / TPB;

    node1_kernel<<<node_blocks, TPB>>>(x, We1, be1, root1, b1);
    edge_kernel<<<edge_blocks, TPB>>>(ei, ea, 0);
    node2_kernel<<<node_blocks, TPB>>>(We2, be2, root2, b2);
    edge_kernel<<<edge_blocks, TPB>>>(ei, ea, 1);
    out_init_kernel<<<(NUM_GRAPHS + TPB - 1) / TPB, TPB>>>(blast, out);
    final_kernel<<<fin_blocks, TPB>>>(batch, Wlast, out);
}